// round 6
// baseline (speedup 1.0000x reference)
#include <cuda_runtime.h>
#include <cstdint>

#define G        25
#define KIN      15
#define KOUT     3
#define XDIM     (G * KIN)        // 375
#define ODIM     (G * KOUT)       // 75

#define ROWS_PER_TILE  4
#define THREADS        128
#define NWARPS         (THREADS / 32)              // 4 -> 1 row per warp
#define STAGES         4
#define TILE_F4        (ROWS_PER_TILE * XDIM / 4)  // 375 float4 per tile
#define GRID_CTAS      888                         // 6 per SM * 148

__device__ __forceinline__ void cp_async16(void* smem_dst, const void* gmem_src) {
    uint32_t s = (uint32_t)__cvta_generic_to_shared(smem_dst);
    asm volatile("cp.async.cg.shared.global [%0], [%1], 16;\n" :: "r"(s), "l"(gmem_src));
}
__device__ __forceinline__ void cp_async_commit() {
    asm volatile("cp.async.commit_group;\n" ::: "memory");
}
__device__ __forceinline__ void cp_async_wait2() {
    asm volatile("cp.async.wait_group 2;\n" ::: "memory");
}

__global__ __launch_bounds__(THREADS, 6)
void mlp_rsna4_kernel(const float* __restrict__ x,
                      const float* __restrict__ W,
                      const int*   __restrict__ k_idx,
                      const int*   __restrict__ v_idx,
                      float* __restrict__ out,
                      int ntiles)
{
    __shared__ float sx[STAGES][ROWS_PER_TILE * XDIM];   // 4 * 6000 B = 24 KB

    const int tid  = threadIdx.x;
    const int wrp  = tid >> 5;
    const int lane = tid & 31;
    const bool active = (lane < G);
    const int g = lane;
    const int grid = (int)gridDim.x;

    // ---- Per-thread persistent state ----
    float wreg[KOUT * KIN];   // 45
    int   ki[KIN];            // 15
    int   vi[KOUT];           // 3
    if (active) {
        #pragma unroll
        for (int i = 0; i < KOUT * KIN; i++) wreg[i] = W[g * KOUT * KIN + i];
        #pragma unroll
        for (int i = 0; i < KIN; i++) ki[i] = k_idx[g * KIN + i];
        #pragma unroll
        for (int o = 0; o < KOUT; o++) vi[o] = v_idx[g * KOUT + o];
    }

    // ---- Prologue: prefetch up to 3 tiles ahead ----
    const int tile0 = blockIdx.x;
    #pragma unroll
    for (int s = 0; s < STAGES - 1; s++) {
        const int t = tile0 + s * grid;
        if (t < ntiles) {
            const float4* __restrict__ xin =
                (const float4*)(x + (long long)t * ROWS_PER_TILE * XDIM);
            #pragma unroll
            for (int i = tid; i < TILE_F4; i += THREADS)
                cp_async16(&sx[s][i * 4], xin + i);
        }
        cp_async_commit();
    }

    // ---- Main loop: 1 barrier per tile ----
    int s = 0;
    for (int tile = tile0; tile < ntiles; tile += grid) {
        cp_async_wait2();         // group for buf s retired (<=2 pending)
        __syncthreads();          // publish buf s to all warps; fence prior
                                  // compute before buf (s+3)&3 is overwritten

        // Prefetch tile+3*grid into buf (s+3)&3 (consumed last iteration)
        {
            const int pf = tile + (STAGES - 1) * grid;
            if (pf < ntiles) {
                const float4* __restrict__ xin =
                    (const float4*)(x + (long long)pf * ROWS_PER_TILE * XDIM);
                float* dst = sx[(s + STAGES - 1) & (STAGES - 1)];
                #pragma unroll
                for (int i = tid; i < TILE_F4; i += THREADS)
                    cp_async16(dst + i * 4, xin + i);
            }
            cp_async_commit();
        }

        // Compute: each warp owns one row of the 4-row tile
        if (active) {
            const float* __restrict__ xr = sx[s] + wrp * XDIM;

            float a0 = 0.f, a1 = 0.f, a2 = 0.f;
            #pragma unroll
            for (int i = 0; i < KIN; i++) {
                const float xv = xr[ki[i]];      // stride-15 gather: conflict-free
                a0 = fmaf(xv, wreg[i],            a0);
                a1 = fmaf(xv, wreg[KIN + i],      a1);
                a2 = fmaf(xv, wreg[2 * KIN + i],  a2);
            }

            const long long obase =
                ((long long)tile * ROWS_PER_TILE + wrp) * ODIM;
            out[obase + vi[0]] = a0;
            out[obase + vi[1]] = a1;
            out[obase + vi[2]] = a2;
        }

        s = (s + 1) & (STAGES - 1);
    }
}

extern "C" void kernel_launch(void* const* d_in, const int* in_sizes, int n_in,
                              void* d_out, int out_size)
{
    const float* x     = (const float*)d_in[0];
    const float* W     = (const float*)d_in[1];
    const int*   k_idx = (const int*)d_in[2];
    const int*   v_idx = (const int*)d_in[3];
    float* out = (float*)d_out;

    const int b_rows = in_sizes[0] / XDIM;          // 262144
    const int ntiles = b_rows / ROWS_PER_TILE;      // 65536

    int grid = GRID_CTAS;
    if (grid > ntiles) grid = ntiles;
    mlp_rsna4_kernel<<<grid, THREADS>>>(x, W, k_idx, v_idx, out, ntiles);
}

// round 7
// speedup vs baseline: 1.2047x; 1.2047x over previous
#include <cuda_runtime.h>
#include <cstdint>

#define G        25
#define KIN      15
#define KOUT     3
#define XDIM     (G * KIN)        // 375
#define ODIM     (G * KOUT)       // 75

#define ROWS_PER_TILE  16
#define THREADS        384
#define NWARPS         (THREADS / 32)              // 12 = 3 o-roles x 4 row-slots
#define ROWS_PER_SLOT  (ROWS_PER_TILE / 4)         // 4 rows per warp
#define TILE_F4        (ROWS_PER_TILE * XDIM / 4)  // 1500 float4 per tile
#define OUT_F4         (ROWS_PER_TILE * ODIM / 4)  // 300 float4 per tile
#define GRID_CTAS      444                          // 3 per SM * 148

__device__ __forceinline__ void cp_async16(void* smem_dst, const void* gmem_src) {
    uint32_t s = (uint32_t)__cvta_generic_to_shared(smem_dst);
    asm volatile("cp.async.cg.shared.global [%0], [%1], 16;\n" :: "r"(s), "l"(gmem_src));
}
__device__ __forceinline__ void cp_async_commit() {
    asm volatile("cp.async.commit_group;\n" ::: "memory");
}
__device__ __forceinline__ void cp_async_wait1() {
    asm volatile("cp.async.wait_group 1;\n" ::: "memory");
}

__global__ __launch_bounds__(THREADS, 3)
void mlp_rsna4_kernel(const float* __restrict__ x,
                      const float* __restrict__ W,
                      const int*   __restrict__ k_idx,
                      const int*   __restrict__ v_idx,
                      float* __restrict__ out,
                      int ntiles)
{
    __shared__ float sx[2][ROWS_PER_TILE * XDIM];   // 48000 B
    __shared__ float sout[ROWS_PER_TILE * ODIM];    //  4800 B

    const int tid  = threadIdx.x;
    const int wrp  = tid >> 5;
    const int lane = tid & 31;
    const bool active = (lane < G);
    const int g      = lane;        // group owned by this lane
    const int o_role = wrp >> 2;    // 0..2  : which of the 3 outputs
    const int rslot  = wrp & 3;     // 0..3  : row slot within tile

    // ---- Per-thread persistent state: ONE (g,o) pair -> 31 regs ----
    float wreg[KIN];   // 15
    int   ki[KIN];     // 15
    int   vi_o = 0;    // 1
    if (active) {
        #pragma unroll
        for (int i = 0; i < KIN; i++)
            wreg[i] = W[(g * KOUT + o_role) * KIN + i];
        #pragma unroll
        for (int i = 0; i < KIN; i++) ki[i] = k_idx[g * KIN + i];
        vi_o = v_idx[g * KOUT + o_role];
    }

    // ---- Prefetch first tile into buffer 0 ----
    int tile = blockIdx.x;
    int buf = 0;
    if (tile < ntiles) {
        const float4* __restrict__ xin =
            (const float4*)(x + (long long)tile * ROWS_PER_TILE * XDIM);
        #pragma unroll
        for (int i = tid; i < TILE_F4; i += THREADS)
            cp_async16(&sx[0][i * 4], xin + i);
    }
    cp_async_commit();

    // ---- Pipelined grid-stride loop (R5 skeleton) ----
    for (; tile < ntiles; tile += gridDim.x) {
        const int next = tile + gridDim.x;
        if (next < ntiles) {
            const float4* __restrict__ xin =
                (const float4*)(x + (long long)next * ROWS_PER_TILE * XDIM);
            #pragma unroll
            for (int i = tid; i < TILE_F4; i += THREADS)
                cp_async16(&sx[buf ^ 1][i * 4], xin + i);
        }
        cp_async_commit();        // next-tile group in flight
        cp_async_wait1();         // current tile complete
        __syncthreads();          // publish x; prior flush done

        if (active) {
            #pragma unroll
            for (int rr = 0; rr < ROWS_PER_SLOT; rr++) {
                const int r = rslot + rr * 4;
                const float* __restrict__ xr = sx[buf] + r * XDIM;

                float acc = 0.f;
                #pragma unroll
                for (int i = 0; i < KIN; i++)
                    acc = fmaf(xr[ki[i]], wreg[i], acc);  // stride-15: conflict-free

                sout[r * ODIM + vi_o] = acc;              // stride-3: conflict-free
            }
        }

        __syncthreads();          // sout complete

        // Coalesced vectorized flush: 4800 B contiguous span
        {
            const float4* __restrict__ so4 = (const float4*)sout;
            float4* __restrict__ o4 =
                (float4*)(out + (long long)tile * ROWS_PER_TILE * ODIM);
            #pragma unroll
            for (int i = tid; i < OUT_F4; i += THREADS)
                o4[i] = so4[i];
        }

        __syncthreads();          // reads of sx[buf]/sout done before reuse
        buf ^= 1;
    }
}

extern "C" void kernel_launch(void* const* d_in, const int* in_sizes, int n_in,
                              void* d_out, int out_size)
{
    const float* x     = (const float*)d_in[0];
    const float* W     = (const float*)d_in[1];
    const int*   k_idx = (const int*)d_in[2];
    const int*   v_idx = (const int*)d_in[3];
    float* out = (float*)d_out;

    const int b_rows = in_sizes[0] / XDIM;          // 262144
    const int ntiles = b_rows / ROWS_PER_TILE;      // 16384

    int grid = GRID_CTAS;
    if (grid > ntiles) grid = ntiles;
    mlp_rsna4_kernel<<<grid, THREADS>>>(x, W, k_idx, v_idx, out, ntiles);
}